// round 10
// baseline (speedup 1.0000x reference)
#include <cuda_runtime.h>
#include <math.h>

#define NRAYS 2048
#define TOT 128
#define INDS 16
#define HID 64
#define MTOT (NRAYS*TOT)
#define EPSF 1e-8f

typedef unsigned long long u64;

// ---------------- f32x2 packed helpers (sm_103a) ----------------
__device__ __forceinline__ u64 pk2(float lo, float hi) {
    u64 r; asm("mov.b64 %0, {%1,%2};" : "=l"(r) : "f"(lo), "f"(hi)); return r;
}
__device__ __forceinline__ u64 bc2(float v) {
    u64 r; asm("mov.b64 %0, {%1,%1};" : "=l"(r) : "f"(v)); return r;
}
__device__ __forceinline__ void upk2(u64 a, float& lo, float& hi) {
    asm("mov.b64 {%0,%1}, %2;" : "=f"(lo), "=f"(hi) : "l"(a));
}
__device__ __forceinline__ u64 fma2(u64 a, u64 b, u64 c) {
    u64 d; asm("fma.rn.f32x2 %0, %1, %2, %3;" : "=l"(d) : "l"(a), "l"(b), "l"(c)); return d;
}
__device__ __forceinline__ u64 mul2(u64 a, u64 b) {
    u64 d; asm("mul.rn.f32x2 %0, %1, %2;" : "=l"(d) : "l"(a), "l"(b)); return d;
}

// MUFU sin pair: 2 SFU-pipe instructions, zero FMA-pipe cost.
__device__ __forceinline__ u64 sin2_mufu(u64 x) {
    float lo, hi; upk2(x, lo, hi);
    return pk2(__sinf(lo), __sinf(hi));
}

// Scalar FMA-pipe sin: reduce mod 2*pi, degree-11 odd minimax on [-pi,pi].
// Multiplier constants (1/2pi, -2pi, c11) are FFMA immediates (0 regs, rt=1);
// only the 5 addend constants take registers — shared across both calls.
__device__ __forceinline__ float sin_poly(float x) {
    float t = fmaf(x, 0.15915494309189535f, 12582912.0f);  // round(x/2pi)
    float k = t - 12582912.0f;
    float r = fmaf(k, -6.28318548202514648f, x);            // r in [-pi,pi]
    float s = r * r;
    float u = fmaf(-2.3889859e-08f, s, 2.7525562e-06f);
    u = fmaf(u, s, -0.00019840874f);
    u = fmaf(u, s, 0.0083333310f);
    u = fmaf(u, s, -0.16666667f);
    return fmaf(s * r, u, r);
}
__device__ __forceinline__ u64 sin2_poly(u64 x) {
    float lo, hi; upk2(x, lo, hi);
    return pk2(sin_poly(lo), sin_poly(hi));
}

// ---------------- scalar helpers ----------------
__device__ __forceinline__ float tanh_fast(float x) {
    float ax = fminf(fabsf(x), 10.0f);
    float e = __expf(2.0f * ax);
    float t = __fdividef(e - 1.0f, e + 1.0f);
    return (x < 0.0f) ? -t : t;
}
__device__ __forceinline__ float softplus_acc(float x) {
    return fmaxf(x, 0.0f) + log1pf(expf(-fabsf(x)));
}
__device__ __forceinline__ float sigmoid_acc(float x) {
    float e = expf(-fabsf(x));
    float r = 1.0f / (1.0f + e);
    return (x >= 0.0f) ? r : (e / (1.0f + e));
}

// ---------------- env map bilinear sample ----------------
__device__ __forceinline__ void sample_env(const float* __restrict__ env,
                                           float px, float py, float pz,
                                           float& Le0, float& Le1, float& Le2) {
    const float INV_PI = 0.3183098861837907f;
    float theta = atan2f(px, -pz);
    if (isnan(theta)) theta = 0.0f;
    theta *= INV_PI;
    float ac = acosf(py);
    if (isnan(ac)) ac = 0.0f;
    float phi = fmaf(ac, 2.0f * INV_PI, -1.0f);

    float ix = ((theta + 1.0f) * 256.0f - 1.0f) * 0.5f;
    float iy = ((phi   + 1.0f) * 128.0f - 1.0f) * 0.5f;
    float x0 = floorf(ix), y0 = floorf(iy);
    float wx = ix - x0,    wy = iy - y0;

    float v0 = 0.0f, v1 = 0.0f, v2 = 0.0f;
    #pragma unroll
    for (int t = 0; t < 4; t++) {
        float xc = x0 + (float)(t & 1);
        float yc = y0 + (float)(t >> 1);
        float w = ((t & 1) ? wx : (1.0f - wx)) * ((t >> 1) ? wy : (1.0f - wy));
        bool inb = (xc >= 0.0f) && (xc < 256.0f) && (yc >= 0.0f) && (yc < 128.0f);
        float wi = inb ? w : 0.0f;
        int xi = (int)fminf(fmaxf(xc, 0.0f), 255.0f);
        int yi = (int)fminf(fmaxf(yc, 0.0f), 127.0f);
        int base = yi * 256 + xi;
        v0 = fmaf(wi, env[base],         v0);
        v1 = fmaf(wi, env[32768 + base], v1);
        v2 = fmaf(wi, env[65536 + base], v2);
    }
    Le0 = expf(v0); Le1 = expf(v1); Le2 = expf(v2);
}

__device__ __forceinline__ u64 dup_bits(float v) {
    u64 b = (u64)__float_as_uint(v);
    return b | (b << 32);
}

// j-iteration, per-thread base/slope (depth 1). 7 MUFU pairs + 1 FMA-poly pair.
__device__ __forceinline__ void jstep(
    int j,
    const float4* __restrict__ sA,
    const ulonglong2* __restrict__ sBxy,
    const u64* __restrict__ sBz,
    float ox, float oy, float oz, float dx, float dy, float dz,
    const u64* __restrict__ Zp, u64 Acc[8][3])
{
    float4 aa = sA[j];
    float base  = fmaf(ox, aa.x, fmaf(oy, aa.y, oz * aa.z));
    float slope = fmaf(dx, aa.x, fmaf(dy, aa.y, dz * aa.z));
    u64 base2  = bc2(base);
    u64 slope2 = bc2(slope);
    ulonglong2 bxy = sBxy[j];
    u64 bz = sBz[j];

    u64 H[8];
    #pragma unroll
    for (int p = 0; p < 7; p++)
        H[p] = sin2_mufu(fma2(Zp[p], slope2, base2));
    H[7] = sin2_poly(fma2(Zp[7], slope2, base2));

    #pragma unroll
    for (int p = 0; p < 8; p++) {
        Acc[p][0] = fma2(H[p], bxy.x, Acc[p][0]);
        Acc[p][1] = fma2(H[p], bxy.y, Acc[p][1]);
        Acc[p][2] = fma2(H[p], bz,    Acc[p][2]);
    }
}

// j-iteration, block-uniform base/slope (depth 0). 7 MUFU + 1 FMA-poly pair.
__device__ __forceinline__ void jstep_pre(
    int j,
    const float2* __restrict__ sBS,
    const ulonglong2* __restrict__ sBxy,
    const u64* __restrict__ sBz,
    const u64* __restrict__ Zp, u64 Acc[8][3])
{
    float2 bs = sBS[j];
    u64 base2  = bc2(bs.x);
    u64 slope2 = bc2(bs.y);
    ulonglong2 bxy = sBxy[j];
    u64 bz = sBz[j];

    u64 H[8];
    #pragma unroll
    for (int p = 0; p < 7; p++)
        H[p] = sin2_mufu(fma2(Zp[p], slope2, base2));
    H[7] = sin2_poly(fma2(Zp[7], slope2, base2));

    #pragma unroll
    for (int p = 0; p < 8; p++) {
        Acc[p][0] = fma2(H[p], bxy.x, Acc[p][0]);
        Acc[p][1] = fma2(H[p], bxy.y, Acc[p][1]);
        Acc[p][2] = fma2(H[p], bz,    Acc[p][2]);
    }
}

// ---------------- main fused renderer: 1 block = 1 ray, 1 thread = 1 sample ----------------
__global__ __launch_bounds__(TOT, 5)
void nerf_render_kernel(
    const float* __restrict__ rays_o, const float* __restrict__ rays_d,
    const float* __restrict__ env,
    const float* __restrict__ gWd1, const float* __restrict__ gWd2,
    const float* __restrict__ gWf1, const float* __restrict__ gWs,
    const float* __restrict__ gWdir, const float* __restrict__ gWrho,
    const float* __restrict__ jitter, const float* __restrict__ u_t,
    const float* __restrict__ u_scatter, const int* __restrict__ channel,
    float* __restrict__ out)
{
    __shared__ float4 sA[HID];          // Wd1 col j: ax, ay, az, 0
    __shared__ ulonglong2 sBxy[HID];    // Wd2 row j: bx dup, by dup
    __shared__ u64 sBz[HID];            // Wd2 row j: bz dup
    __shared__ float2 sBS[HID];         // depth-0 block-uniform {base_j, slope_j}
    __shared__ float4 sF0[HID];         // Wf1 col j, elems 0..3
    __shared__ float2 sF1[HID];         // Wf1 col j, elems 4..5
    __shared__ float4 sO0[HID];         // Ws[j][0..2], Wdir[j][0]
    __shared__ float4 sO1[HID];         // Wdir[j][1..2], Wrho[j][0..1]
    __shared__ float  sO2[HID];         // Wrho[j][2]
    __shared__ float  red[4][3];

    int tid = threadIdx.x;
    if (tid < HID) {
        int j = tid;
        sA[j]   = make_float4(gWd1[j], gWd1[64 + j], gWd1[128 + j], 0.0f);
        sBxy[j] = make_ulonglong2(dup_bits(gWd2[j * 3]), dup_bits(gWd2[j * 3 + 1]));
        sBz[j]  = dup_bits(gWd2[j * 3 + 2]);
        sF0[j] = make_float4(gWf1[j], gWf1[64 + j], gWf1[128 + j], gWf1[192 + j]);
        sF1[j] = make_float2(gWf1[256 + j], gWf1[320 + j]);
        sO0[j] = make_float4(gWs[j * 3], gWs[j * 3 + 1], gWs[j * 3 + 2], gWdir[j * 3]);
        sO1[j] = make_float4(gWdir[j * 3 + 1], gWdir[j * 3 + 2], gWrho[j * 3], gWrho[j * 3 + 1]);
        sO2[j] = gWrho[j * 3 + 2];
    }
    __syncthreads();

    int ray = blockIdx.x;
    int m = ray * TOT + tid;

    float ox = rays_o[ray * 3 + 0], oy = rays_o[ray * 3 + 1], oz = rays_o[ray * 3 + 2];
    float dx = rays_d[ray * 3 + 0], dy = rays_d[ray * 3 + 1], dz = rays_d[ray * 3 + 2];
    bool alive = true;
    float thr0 = 1.0f, thr1 = 1.0f, thr2 = 1.0f;
    float rgb0 = 0.0f, rgb1 = 0.0f, rgb2 = 0.0f;

    #pragma unroll
    for (int dep = 0; dep < 2; ++dep) {
        // At depth 0, o and d are block-uniform -> base/slope dot products
        // are block-uniform: compute once into smem.
        if (dep == 0) {
            if (tid < HID) {
                float4 aa = sA[tid];
                float base  = fmaf(ox, aa.x, fmaf(oy, aa.y, oz * aa.z));
                float slope = fmaf(dx, aa.x, fmaf(dy, aa.y, dz * aa.z));
                sBS[tid] = make_float2(base, slope);
            }
            __syncthreads();
        }

        // sphere intersection
        float a = dx * dx + dy * dy + dz * dz;
        float b = 2.0f * (dx * ox + dy * oy + dz * oz);
        float c = ox * ox + oy * oy + oz * oz - 1.0f;
        float delta = b * b - 4.0f * a * c;
        alive = alive && (delta > 0.0f);
        float sq = sqrtf(fmaxf(delta, 0.0f));
        float twoa = 2.0f * a;
        float nears = fmaxf((-b - sq) / twoa, 0.001f);
        float fars  = fmaxf((-b + sq) / twoa, 0.001f);
        float span = fars - nears;

        // ---- density over 16 jittered samples ----
        // 7 of 8 packed sin-pairs on the MUFU pipe (112 cyc/j), 1 pair on the
        // FMA pipe via scalar poly (FMA ~104 cyc/j) — pipes balanced at occ 5.
        const float4* jp = (const float4*)(jitter + (size_t)dep * (size_t)MTOT * INDS
                                                  + (size_t)m * INDS);
        u64 Zp[8];
        {
            #pragma unroll
            for (int q = 0; q < 4; q++) {
                float4 jv = jp[q];
                float z0 = nears + span * ((float)(4*q + 0) * (1.0f/15.0f)) + (jv.x - 0.5f) * (span * (1.0f/16.0f));
                float z1 = nears + span * ((float)(4*q + 1) * (1.0f/15.0f)) + (jv.y - 0.5f) * (span * (1.0f/16.0f));
                float z2 = nears + span * ((float)(4*q + 2) * (1.0f/15.0f)) + (jv.z - 0.5f) * (span * (1.0f/16.0f));
                float z3 = nears + span * ((float)(4*q + 3) * (1.0f/15.0f)) + (jv.w - 0.5f) * (span * (1.0f/16.0f));
                Zp[2*q]     = pk2(z0, z1);
                Zp[2*q + 1] = pk2(z2, z3);
            }
        }

        u64 Acc[8][3];
        #pragma unroll
        for (int p = 0; p < 8; p++) { Acc[p][0] = 0; Acc[p][1] = 0; Acc[p][2] = 0; }

        if (dep == 0) {
            #pragma unroll 1
            for (int j = 0; j < HID; j++)
                jstep_pre(j, sBS, sBxy, sBz, Zp, Acc);
        } else {
            #pragma unroll 1
            for (int j = 0; j < HID; j++)
                jstep(j, sA, sBxy, sBz, ox, oy, oz, dx, dy, dz, Zp, Acc);
        }

        // softplus monotone -> reduce raw max per channel, softplus once.
        float rm0 = -1e30f, rm1 = -1e30f, rm2 = -1e30f;
        #pragma unroll
        for (int p = 0; p < 8; p++) {
            float pa, pb;
            upk2(Acc[p][0], pa, pb); rm0 = fmaxf(rm0, fmaxf(pa, pb));
            upk2(Acc[p][1], pa, pb); rm1 = fmaxf(rm1, fmaxf(pa, pb));
            upk2(Acc[p][2], pa, pb); rm2 = fmaxf(rm2, fmaxf(pa, pb));
        }
        float mm0 = fmaxf(softplus_acc(rm0), 0.001f);
        float mm1 = fmaxf(softplus_acc(rm1), 0.001f);
        float mm2 = fmaxf(softplus_acc(rm2), 0.001f);
        float maxm = fmaxf(mm0, fmaxf(mm1, mm2));

        int ch = 0;
        float maj = 0.001f;
        float t;
        if (dep == 0) {
            ch = channel[m];
            maj = (ch == 0) ? mm0 : ((ch == 1) ? mm1 : mm2);
            float ut = u_t[m];
            t = -log1pf(-ut) / maj + nears;
        } else {
            t = fars;
        }
        bool hit = alive && (t >= fars);

        float dn0 = expf(-mm0 * span) / (maxm + EPSF) + EPSF;
        float dn1 = expf(-mm1 * span) / (maxm + EPSF) + EPSF;
        float dn2 = expf(-mm2 * span) / (maxm + EPSF) + EPSF;
        float dmean = (dn0 + dn1 + dn2) * (1.0f / 3.0f);

        float Le0, Le1, Le2;
        sample_env(env, fmaf(dx, fars, ox), fmaf(dy, fars, oy), fmaf(dz, fars, oz),
                   Le0, Le1, Le2);

        if (hit) {
            rgb0 += thr0 * (dn0 / dmean) * Le0;
            rgb1 += thr1 * (dn1 / dmean) * Le1;
            rgb2 += thr2 * (dn2 / dmean) * Le2;
        }
        alive = alive && !hit;

        if (dep == 0) {
            float tr0 = expf(-mm0 * (t - nears)) / maxm;
            float tr1 = expf(-mm1 * (t - nears)) / maxm;
            float tr2 = expf(-mm2 * (t - nears)) / maxm;
            float den2 = (mm0 * tr0 + mm1 * tr1 + mm2 * tr2) * (1.0f / 3.0f);
            if (alive) {
                thr0 = thr0 * tr0 / den2;
                thr1 = thr1 * tr1 / den2;
                thr2 = thr2 * tr2 / den2;
                ox = fmaf(dx, t, ox);
                oy = fmaf(dy, t, oy);
                oz = fmaf(dz, t, oz);
            }
            // material MLP on [o, d] (post-update o)
            float st0 = 0.0f, st1 = 0.0f, st2 = 0.0f;
            float v0 = 0.0f, v1 = 0.0f, v2 = 0.0f;
            float rh0 = 0.0f, rh1 = 0.0f, rh2 = 0.0f;
            #pragma unroll 8
            for (int j = 0; j < HID; j++) {
                float4 w0 = sF0[j];
                float2 w1 = sF1[j];
                float u = fmaf(ox, w0.x, fmaf(oy, w0.y, fmaf(oz, w0.z,
                          fmaf(dx, w0.w, fmaf(dy, w1.x, dz * w1.y)))));
                float f = tanh_fast(u);
                float4 p0 = sO0[j];
                float4 p1 = sO1[j];
                float p2 = sO2[j];
                st0 = fmaf(f, p0.x, st0);
                st1 = fmaf(f, p0.y, st1);
                st2 = fmaf(f, p0.z, st2);
                v0  = fmaf(f, p0.w, v0);
                v1  = fmaf(f, p1.x, v1);
                v2  = fmaf(f, p1.y, v2);
                rh0 = fmaf(f, p1.z, rh0);
                rh1 = fmaf(f, p1.w, rh1);
                rh2 = fmaf(f, p2,   rh2);
            }
            st0 = softplus_acc(st0);
            st1 = softplus_acc(st1);
            st2 = softplus_acc(st2);
            float nrm = sqrtf(v0 * v0 + v1 * v1 + v2 * v2);
            float invn = 1.0f / (nrm + EPSF);
            float do0 = v0 * invn, do1 = v1 * invn, do2 = v2 * invn;
            float rho0 = sigmoid_acc(rh0), rho1 = sigmoid_acc(rh1), rho2 = sigmoid_acc(rh2);

            float stch = (ch == 0) ? st0 : ((ch == 1) ? st1 : st2);
            float sp = fminf(stch / maj, 1.0f);
            float us = u_scatter[m];
            bool sm = alive && (us < sp);
            if (sm) {
                dx = do0; dy = do1; dz = do2;
                thr0 = thr0 / (sp + EPSF) * rho0;
                thr1 = thr1 / (sp + EPSF) * rho1;
                thr2 = thr2 / (sp + EPSF) * rho2;
            } else if (alive) {
                float inv = 1.0f / (1.0f - sp + EPSF);
                thr0 *= inv; thr1 *= inv; thr2 *= inv;
            }
        }
    }

    // block reduce: mean over TOT samples of this ray
    #pragma unroll
    for (int off = 16; off > 0; off >>= 1) {
        rgb0 += __shfl_down_sync(0xffffffffu, rgb0, off);
        rgb1 += __shfl_down_sync(0xffffffffu, rgb1, off);
        rgb2 += __shfl_down_sync(0xffffffffu, rgb2, off);
    }
    if ((tid & 31) == 0) {
        red[tid >> 5][0] = rgb0;
        red[tid >> 5][1] = rgb1;
        red[tid >> 5][2] = rgb2;
    }
    __syncthreads();
    if (tid == 0) {
        float a0 = red[0][0] + red[1][0] + red[2][0] + red[3][0];
        float a1 = red[0][1] + red[1][1] + red[2][1] + red[3][1];
        float a2 = red[0][2] + red[1][2] + red[2][2] + red[3][2];
        out[ray * 3 + 0] = a0 * (1.0f / (float)TOT);
        out[ray * 3 + 1] = a1 * (1.0f / (float)TOT);
        out[ray * 3 + 2] = a2 * (1.0f / (float)TOT);
    }
}

extern "C" void kernel_launch(void* const* d_in, const int* in_sizes, int n_in,
                              void* d_out, int out_size) {
    const float* rays_o    = (const float*)d_in[0];
    const float* rays_d    = (const float*)d_in[1];
    const float* env       = (const float*)d_in[2];
    const float* Wd1       = (const float*)d_in[3];
    const float* Wd2       = (const float*)d_in[4];
    const float* Wf1       = (const float*)d_in[5];
    const float* Ws        = (const float*)d_in[6];
    const float* Wdir      = (const float*)d_in[7];
    const float* Wrho      = (const float*)d_in[8];
    const float* jitter    = (const float*)d_in[9];
    const float* u_t       = (const float*)d_in[10];
    const float* u_scatter = (const float*)d_in[11];
    const int*   channel   = (const int*)d_in[12];
    float* out = (float*)d_out;

    nerf_render_kernel<<<NRAYS, TOT>>>(rays_o, rays_d, env, Wd1, Wd2, Wf1, Ws,
                                       Wdir, Wrho, jitter, u_t, u_scatter,
                                       channel, out);
}

// round 11
// speedup vs baseline: 1.0788x; 1.0788x over previous
#include <cuda_runtime.h>
#include <math.h>

#define NRAYS 2048
#define TOT 128
#define INDS 16
#define HID 64
#define MTOT (NRAYS*TOT)
#define EPSF 1e-8f

typedef unsigned long long u64;

// ---------------- f32x2 packed helpers (sm_103a) ----------------
__device__ __forceinline__ u64 pk2(float lo, float hi) {
    u64 r; asm("mov.b64 %0, {%1,%2};" : "=l"(r) : "f"(lo), "f"(hi)); return r;
}
__device__ __forceinline__ u64 bc2(float v) {
    u64 r; asm("mov.b64 %0, {%1,%1};" : "=l"(r) : "f"(v)); return r;
}
__device__ __forceinline__ void upk2(u64 a, float& lo, float& hi) {
    asm("mov.b64 {%0,%1}, %2;" : "=f"(lo), "=f"(hi) : "l"(a));
}
__device__ __forceinline__ u64 fma2(u64 a, u64 b, u64 c) {
    u64 d; asm("fma.rn.f32x2 %0, %1, %2, %3;" : "=l"(d) : "l"(a), "l"(b), "l"(c)); return d;
}

// MUFU sin pair: 2 SFU-pipe instructions, zero FMA-pipe cost.
__device__ __forceinline__ u64 sin2_mufu(u64 x) {
    float lo, hi; upk2(x, lo, hi);
    return pk2(__sinf(lo), __sinf(hi));
}

// ---------------- scalar helpers (fast-math epilogue) ----------------
__device__ __forceinline__ float tanh_fast(float x) {
    float ax = fminf(fabsf(x), 10.0f);
    float e = __expf(2.0f * ax);
    float t = __fdividef(e - 1.0f, e + 1.0f);
    return (x < 0.0f) ? -t : t;
}
__device__ __forceinline__ float softplus_fast(float x) {
    return fmaxf(x, 0.0f) + __logf(1.0f + __expf(-fabsf(x)));
}
__device__ __forceinline__ float sigmoid_fast(float x) {
    float e = __expf(-fabsf(x));
    float r = __fdividef(1.0f, 1.0f + e);
    return (x >= 0.0f) ? r : (1.0f - r);
}

// ---------------- env map bilinear sample ----------------
__device__ __forceinline__ void sample_env(const float* __restrict__ env,
                                           float px, float py, float pz,
                                           float& Le0, float& Le1, float& Le2) {
    const float INV_PI = 0.3183098861837907f;
    float theta = atan2f(px, -pz);
    if (isnan(theta)) theta = 0.0f;
    theta *= INV_PI;
    float ac = acosf(py);
    if (isnan(ac)) ac = 0.0f;
    float phi = fmaf(ac, 2.0f * INV_PI, -1.0f);

    float ix = ((theta + 1.0f) * 256.0f - 1.0f) * 0.5f;
    float iy = ((phi   + 1.0f) * 128.0f - 1.0f) * 0.5f;
    float x0 = floorf(ix), y0 = floorf(iy);
    float wx = ix - x0,    wy = iy - y0;

    float v0 = 0.0f, v1 = 0.0f, v2 = 0.0f;
    #pragma unroll
    for (int t = 0; t < 4; t++) {
        float xc = x0 + (float)(t & 1);
        float yc = y0 + (float)(t >> 1);
        float w = ((t & 1) ? wx : (1.0f - wx)) * ((t >> 1) ? wy : (1.0f - wy));
        bool inb = (xc >= 0.0f) && (xc < 256.0f) && (yc >= 0.0f) && (yc < 128.0f);
        float wi = inb ? w : 0.0f;
        int xi = (int)fminf(fmaxf(xc, 0.0f), 255.0f);
        int yi = (int)fminf(fmaxf(yc, 0.0f), 127.0f);
        int base = yi * 256 + xi;
        v0 = fmaf(wi, env[base],         v0);
        v1 = fmaf(wi, env[32768 + base], v1);
        v2 = fmaf(wi, env[65536 + base], v2);
    }
    Le0 = __expf(v0); Le1 = __expf(v1); Le2 = __expf(v2);
}

__device__ __forceinline__ u64 dup_bits(float v) {
    u64 b = (u64)__float_as_uint(v);
    return b | (b << 32);
}

// ---------------- main fused renderer: 1 block = 1 ray, 1 thread = 1 sample ----------------
// Zp lives in shared memory (thread-private slots, conflict-free layout) to
// cut 16 registers -> 6 blocks/SM: more co-resident warps to keep the MUFU
// pipe (the binder) fed.
__global__ __launch_bounds__(TOT, 6)
void nerf_render_kernel(
    const float* __restrict__ rays_o, const float* __restrict__ rays_d,
    const float* __restrict__ env,
    const float* __restrict__ gWd1, const float* __restrict__ gWd2,
    const float* __restrict__ gWf1, const float* __restrict__ gWs,
    const float* __restrict__ gWdir, const float* __restrict__ gWrho,
    const float* __restrict__ jitter, const float* __restrict__ u_t,
    const float* __restrict__ u_scatter, const int* __restrict__ channel,
    float* __restrict__ out)
{
    __shared__ float4 sA[HID];          // Wd1 col j: ax, ay, az, 0
    __shared__ ulonglong2 sBxy[HID];    // Wd2 row j: bx dup, by dup
    __shared__ u64 sBz[HID];            // Wd2 row j: bz dup
    __shared__ float2 sBS[HID];         // depth-0 block-uniform {base_j, slope_j}
    __shared__ float4 sF0[HID];         // Wf1 col j, elems 0..3
    __shared__ float2 sF1[HID];         // Wf1 col j, elems 4..5
    __shared__ float4 sO0[HID];         // Ws[j][0..2], Wdir[j][0]
    __shared__ float4 sO1[HID];         // Wdir[j][1..2], Wrho[j][0..1]
    __shared__ float  sO2[HID];         // Wrho[j][2]
    __shared__ u64    sZp[8][TOT];      // packed z-pairs, [p][tid]: 8B stride -> conflict-free
    __shared__ float  red[4][3];

    int tid = threadIdx.x;
    if (tid < HID) {
        int j = tid;
        sA[j]   = make_float4(gWd1[j], gWd1[64 + j], gWd1[128 + j], 0.0f);
        sBxy[j] = make_ulonglong2(dup_bits(gWd2[j * 3]), dup_bits(gWd2[j * 3 + 1]));
        sBz[j]  = dup_bits(gWd2[j * 3 + 2]);
        sF0[j] = make_float4(gWf1[j], gWf1[64 + j], gWf1[128 + j], gWf1[192 + j]);
        sF1[j] = make_float2(gWf1[256 + j], gWf1[320 + j]);
        sO0[j] = make_float4(gWs[j * 3], gWs[j * 3 + 1], gWs[j * 3 + 2], gWdir[j * 3]);
        sO1[j] = make_float4(gWdir[j * 3 + 1], gWdir[j * 3 + 2], gWrho[j * 3], gWrho[j * 3 + 1]);
        sO2[j] = gWrho[j * 3 + 2];
    }
    __syncthreads();

    int ray = blockIdx.x;
    int m = ray * TOT + tid;

    float ox = rays_o[ray * 3 + 0], oy = rays_o[ray * 3 + 1], oz = rays_o[ray * 3 + 2];
    float dx = rays_d[ray * 3 + 0], dy = rays_d[ray * 3 + 1], dz = rays_d[ray * 3 + 2];
    bool alive = true;
    float thr0 = 1.0f, thr1 = 1.0f, thr2 = 1.0f;
    float rgb0 = 0.0f, rgb1 = 0.0f, rgb2 = 0.0f;

    #pragma unroll
    for (int dep = 0; dep < 2; ++dep) {
        // At depth 0, o and d are block-uniform -> base/slope dot products
        // are block-uniform: compute once into smem.
        if (dep == 0) {
            if (tid < HID) {
                float4 aa = sA[tid];
                float base  = fmaf(ox, aa.x, fmaf(oy, aa.y, oz * aa.z));
                float slope = fmaf(dx, aa.x, fmaf(dy, aa.y, dz * aa.z));
                sBS[tid] = make_float2(base, slope);
            }
            __syncthreads();
        }

        // sphere intersection
        float a = dx * dx + dy * dy + dz * dz;
        float b = 2.0f * (dx * ox + dy * oy + dz * oz);
        float c = ox * ox + oy * oy + oz * oz - 1.0f;
        float delta = b * b - 4.0f * a * c;
        alive = alive && (delta > 0.0f);
        float sq = sqrtf(fmaxf(delta, 0.0f));
        float twoa = 2.0f * a;
        float nears = fmaxf((-b - sq) / twoa, 0.001f);
        float fars  = fmaxf((-b + sq) / twoa, 0.001f);
        float span = fars - nears;

        // ---- density over 16 jittered samples, all sins on the MUFU pipe ----
        // z-pairs parked in smem (thread-private slots) to save 16 registers.
        const float4* jp = (const float4*)(jitter + (size_t)dep * (size_t)MTOT * INDS
                                                  + (size_t)m * INDS);
        {
            #pragma unroll
            for (int q = 0; q < 4; q++) {
                float4 jv = jp[q];
                float z0 = nears + span * ((float)(4*q + 0) * (1.0f/15.0f)) + (jv.x - 0.5f) * (span * (1.0f/16.0f));
                float z1 = nears + span * ((float)(4*q + 1) * (1.0f/15.0f)) + (jv.y - 0.5f) * (span * (1.0f/16.0f));
                float z2 = nears + span * ((float)(4*q + 2) * (1.0f/15.0f)) + (jv.z - 0.5f) * (span * (1.0f/16.0f));
                float z3 = nears + span * ((float)(4*q + 3) * (1.0f/15.0f)) + (jv.w - 0.5f) * (span * (1.0f/16.0f));
                sZp[2*q][tid]     = pk2(z0, z1);
                sZp[2*q + 1][tid] = pk2(z2, z3);
            }
        }

        u64 Acc[8][3];
        #pragma unroll
        for (int p = 0; p < 8; p++) { Acc[p][0] = 0; Acc[p][1] = 0; Acc[p][2] = 0; }

        if (dep == 0) {
            #pragma unroll 1
            for (int j = 0; j < HID; j++) {
                float2 bs = sBS[j];
                u64 base2  = bc2(bs.x);
                u64 slope2 = bc2(bs.y);
                ulonglong2 bxy = sBxy[j];
                u64 bz = sBz[j];
                u64 H[8];
                #pragma unroll
                for (int p = 0; p < 8; p++)
                    H[p] = sin2_mufu(fma2(sZp[p][tid], slope2, base2));
                #pragma unroll
                for (int p = 0; p < 8; p++) {
                    Acc[p][0] = fma2(H[p], bxy.x, Acc[p][0]);
                    Acc[p][1] = fma2(H[p], bxy.y, Acc[p][1]);
                    Acc[p][2] = fma2(H[p], bz,    Acc[p][2]);
                }
            }
        } else {
            #pragma unroll 1
            for (int j = 0; j < HID; j++) {
                float4 aa = sA[j];
                float base  = fmaf(ox, aa.x, fmaf(oy, aa.y, oz * aa.z));
                float slope = fmaf(dx, aa.x, fmaf(dy, aa.y, dz * aa.z));
                u64 base2  = bc2(base);
                u64 slope2 = bc2(slope);
                ulonglong2 bxy = sBxy[j];
                u64 bz = sBz[j];
                u64 H[8];
                #pragma unroll
                for (int p = 0; p < 8; p++)
                    H[p] = sin2_mufu(fma2(sZp[p][tid], slope2, base2));
                #pragma unroll
                for (int p = 0; p < 8; p++) {
                    Acc[p][0] = fma2(H[p], bxy.x, Acc[p][0]);
                    Acc[p][1] = fma2(H[p], bxy.y, Acc[p][1]);
                    Acc[p][2] = fma2(H[p], bz,    Acc[p][2]);
                }
            }
        }

        // softplus monotone -> reduce raw max per channel, softplus once.
        float rm0 = -1e30f, rm1 = -1e30f, rm2 = -1e30f;
        #pragma unroll
        for (int p = 0; p < 8; p++) {
            float pa, pb;
            upk2(Acc[p][0], pa, pb); rm0 = fmaxf(rm0, fmaxf(pa, pb));
            upk2(Acc[p][1], pa, pb); rm1 = fmaxf(rm1, fmaxf(pa, pb));
            upk2(Acc[p][2], pa, pb); rm2 = fmaxf(rm2, fmaxf(pa, pb));
        }
        float mm0 = fmaxf(softplus_fast(rm0), 0.001f);
        float mm1 = fmaxf(softplus_fast(rm1), 0.001f);
        float mm2 = fmaxf(softplus_fast(rm2), 0.001f);
        float maxm = fmaxf(mm0, fmaxf(mm1, mm2));

        int ch = 0;
        float maj = 0.001f;
        float t;
        if (dep == 0) {
            ch = channel[m];
            maj = (ch == 0) ? mm0 : ((ch == 1) ? mm1 : mm2);
            float ut = u_t[m];
            t = -log1pf(-ut) / maj + nears;   // keep accurate: decides `hit`
        } else {
            t = fars;
        }
        bool hit = alive && (t >= fars);

        float dn0 = __expf(-mm0 * span) / (maxm + EPSF) + EPSF;
        float dn1 = __expf(-mm1 * span) / (maxm + EPSF) + EPSF;
        float dn2 = __expf(-mm2 * span) / (maxm + EPSF) + EPSF;
        float dmean = (dn0 + dn1 + dn2) * (1.0f / 3.0f);

        float Le0, Le1, Le2;
        sample_env(env, fmaf(dx, fars, ox), fmaf(dy, fars, oy), fmaf(dz, fars, oz),
                   Le0, Le1, Le2);

        if (hit) {
            rgb0 += thr0 * (dn0 / dmean) * Le0;
            rgb1 += thr1 * (dn1 / dmean) * Le1;
            rgb2 += thr2 * (dn2 / dmean) * Le2;
        }
        alive = alive && !hit;

        if (dep == 0) {
            float tr0 = __expf(-mm0 * (t - nears)) / maxm;
            float tr1 = __expf(-mm1 * (t - nears)) / maxm;
            float tr2 = __expf(-mm2 * (t - nears)) / maxm;
            float den2 = (mm0 * tr0 + mm1 * tr1 + mm2 * tr2) * (1.0f / 3.0f);
            if (alive) {
                thr0 = thr0 * tr0 / den2;
                thr1 = thr1 * tr1 / den2;
                thr2 = thr2 * tr2 / den2;
                ox = fmaf(dx, t, ox);
                oy = fmaf(dy, t, oy);
                oz = fmaf(dz, t, oz);
            }
            // material MLP on [o, d] (post-update o)
            float st0 = 0.0f, st1 = 0.0f, st2 = 0.0f;
            float v0 = 0.0f, v1 = 0.0f, v2 = 0.0f;
            float rh0 = 0.0f, rh1 = 0.0f, rh2 = 0.0f;
            #pragma unroll 8
            for (int j = 0; j < HID; j++) {
                float4 w0 = sF0[j];
                float2 w1 = sF1[j];
                float u = fmaf(ox, w0.x, fmaf(oy, w0.y, fmaf(oz, w0.z,
                          fmaf(dx, w0.w, fmaf(dy, w1.x, dz * w1.y)))));
                float f = tanh_fast(u);
                float4 p0 = sO0[j];
                float4 p1 = sO1[j];
                float p2 = sO2[j];
                st0 = fmaf(f, p0.x, st0);
                st1 = fmaf(f, p0.y, st1);
                st2 = fmaf(f, p0.z, st2);
                v0  = fmaf(f, p0.w, v0);
                v1  = fmaf(f, p1.x, v1);
                v2  = fmaf(f, p1.y, v2);
                rh0 = fmaf(f, p1.z, rh0);
                rh1 = fmaf(f, p1.w, rh1);
                rh2 = fmaf(f, p2,   rh2);
            }
            st0 = softplus_fast(st0);
            st1 = softplus_fast(st1);
            st2 = softplus_fast(st2);
            float nrm = sqrtf(v0 * v0 + v1 * v1 + v2 * v2);
            float invn = 1.0f / (nrm + EPSF);
            float do0 = v0 * invn, do1 = v1 * invn, do2 = v2 * invn;
            float rho0 = sigmoid_fast(rh0), rho1 = sigmoid_fast(rh1), rho2 = sigmoid_fast(rh2);

            float stch = (ch == 0) ? st0 : ((ch == 1) ? st1 : st2);
            float sp = fminf(stch / maj, 1.0f);
            float us = u_scatter[m];
            bool sm = alive && (us < sp);
            if (sm) {
                dx = do0; dy = do1; dz = do2;
                thr0 = thr0 / (sp + EPSF) * rho0;
                thr1 = thr1 / (sp + EPSF) * rho1;
                thr2 = thr2 / (sp + EPSF) * rho2;
            } else if (alive) {
                float inv = 1.0f / (1.0f - sp + EPSF);
                thr0 *= inv; thr1 *= inv; thr2 *= inv;
            }
        }
    }

    // block reduce: mean over TOT samples of this ray
    #pragma unroll
    for (int off = 16; off > 0; off >>= 1) {
        rgb0 += __shfl_down_sync(0xffffffffu, rgb0, off);
        rgb1 += __shfl_down_sync(0xffffffffu, rgb1, off);
        rgb2 += __shfl_down_sync(0xffffffffu, rgb2, off);
    }
    if ((tid & 31) == 0) {
        red[tid >> 5][0] = rgb0;
        red[tid >> 5][1] = rgb1;
        red[tid >> 5][2] = rgb2;
    }
    __syncthreads();
    if (tid == 0) {
        float a0 = red[0][0] + red[1][0] + red[2][0] + red[3][0];
        float a1 = red[0][1] + red[1][1] + red[2][1] + red[3][1];
        float a2 = red[0][2] + red[1][2] + red[2][2] + red[3][2];
        out[ray * 3 + 0] = a0 * (1.0f / (float)TOT);
        out[ray * 3 + 1] = a1 * (1.0f / (float)TOT);
        out[ray * 3 + 2] = a2 * (1.0f / (float)TOT);
    }
}

extern "C" void kernel_launch(void* const* d_in, const int* in_sizes, int n_in,
                              void* d_out, int out_size) {
    const float* rays_o    = (const float*)d_in[0];
    const float* rays_d    = (const float*)d_in[1];
    const float* env       = (const float*)d_in[2];
    const float* Wd1       = (const float*)d_in[3];
    const float* Wd2       = (const float*)d_in[4];
    const float* Wf1       = (const float*)d_in[5];
    const float* Ws        = (const float*)d_in[6];
    const float* Wdir      = (const float*)d_in[7];
    const float* Wrho      = (const float*)d_in[8];
    const float* jitter    = (const float*)d_in[9];
    const float* u_t       = (const float*)d_in[10];
    const float* u_scatter = (const float*)d_in[11];
    const int*   channel   = (const int*)d_in[12];
    float* out = (float*)d_out;

    nerf_render_kernel<<<NRAYS, TOT>>>(rays_o, rays_d, env, Wd1, Wd2, Wf1, Ws,
                                       Wdir, Wrho, jitter, u_t, u_scatter,
                                       channel, out);
}

// round 12
// speedup vs baseline: 1.1039x; 1.0232x over previous
#include <cuda_runtime.h>
#include <math.h>

#define NRAYS 2048
#define TOT 128
#define INDS 16
#define HID 64
#define MTOT (NRAYS*TOT)
#define EPSF 1e-8f

typedef unsigned long long u64;

// ---------------- f32x2 packed helpers (sm_103a) ----------------
__device__ __forceinline__ u64 pk2(float lo, float hi) {
    u64 r; asm("mov.b64 %0, {%1,%2};" : "=l"(r) : "f"(lo), "f"(hi)); return r;
}
__device__ __forceinline__ u64 bc2(float v) {
    u64 r; asm("mov.b64 %0, {%1,%1};" : "=l"(r) : "f"(v)); return r;
}
__device__ __forceinline__ void upk2(u64 a, float& lo, float& hi) {
    asm("mov.b64 {%0,%1}, %2;" : "=f"(lo), "=f"(hi) : "l"(a));
}
__device__ __forceinline__ u64 fma2(u64 a, u64 b, u64 c) {
    u64 d; asm("fma.rn.f32x2 %0, %1, %2, %3;" : "=l"(d) : "l"(a), "l"(b), "l"(c)); return d;
}
__device__ __forceinline__ u64 mul2(u64 a, u64 b) {
    u64 d; asm("mul.rn.f32x2 %0, %1, %2;" : "=l"(d) : "l"(a), "l"(b)); return d;
}

// MUFU sin pair: 2 SFU-pipe instructions, zero FMA-pipe cost.
__device__ __forceinline__ u64 sin2_mufu(u64 x) {
    float lo, hi; upk2(x, lo, hi);
    return pk2(__sinf(lo), __sinf(hi));
}

// ---------------- scalar helpers (fast-math epilogue) ----------------
__device__ __forceinline__ float tanh_fast(float x) {
    float ax = fminf(fabsf(x), 10.0f);
    float e = __expf(2.0f * ax);
    float t = __fdividef(e - 1.0f, e + 1.0f);
    return (x < 0.0f) ? -t : t;
}
__device__ __forceinline__ float softplus_fast(float x) {
    return fmaxf(x, 0.0f) + __logf(1.0f + __expf(-fabsf(x)));
}
__device__ __forceinline__ float sigmoid_fast(float x) {
    float e = __expf(-fabsf(x));
    float r = __fdividef(1.0f, 1.0f + e);
    return (x >= 0.0f) ? r : (1.0f - r);
}

// ---------------- env map bilinear sample ----------------
__device__ __forceinline__ void sample_env(const float* __restrict__ env,
                                           float px, float py, float pz,
                                           float& Le0, float& Le1, float& Le2) {
    const float INV_PI = 0.3183098861837907f;
    float theta = atan2f(px, -pz);
    if (isnan(theta)) theta = 0.0f;
    theta *= INV_PI;
    float ac = acosf(py);
    if (isnan(ac)) ac = 0.0f;
    float phi = fmaf(ac, 2.0f * INV_PI, -1.0f);

    float ix = ((theta + 1.0f) * 256.0f - 1.0f) * 0.5f;
    float iy = ((phi   + 1.0f) * 128.0f - 1.0f) * 0.5f;
    float x0 = floorf(ix), y0 = floorf(iy);
    float wx = ix - x0,    wy = iy - y0;

    float v0 = 0.0f, v1 = 0.0f, v2 = 0.0f;
    #pragma unroll
    for (int t = 0; t < 4; t++) {
        float xc = x0 + (float)(t & 1);
        float yc = y0 + (float)(t >> 1);
        float w = ((t & 1) ? wx : (1.0f - wx)) * ((t >> 1) ? wy : (1.0f - wy));
        bool inb = (xc >= 0.0f) && (xc < 256.0f) && (yc >= 0.0f) && (yc < 128.0f);
        float wi = inb ? w : 0.0f;
        int xi = (int)fminf(fmaxf(xc, 0.0f), 255.0f);
        int yi = (int)fminf(fmaxf(yc, 0.0f), 127.0f);
        int base = yi * 256 + xi;
        v0 = fmaf(wi, env[base],         v0);
        v1 = fmaf(wi, env[32768 + base], v1);
        v2 = fmaf(wi, env[65536 + base], v2);
    }
    Le0 = __expf(v0); Le1 = __expf(v1); Le2 = __expf(v2);
}

__device__ __forceinline__ u64 dup_bits(float v) {
    u64 b = (u64)__float_as_uint(v);
    return b | (b << 32);
}

// ---------------- main fused renderer: 1 block = 1 ray, 1 thread = 1 sample ----------------
// Depth 0: 6 of 8 sample-pairs via MUFU sin; 2 pairs via angle-addition with
// block-uniform sincos(u) table (smem) + tiny-angle poly for the per-thread
// jitter part — MUFU/j 128->96 cyc, FMA/j 64->88 cyc (pipes re-balanced).
// Depth 1: all-MUFU (u is per-thread there; AA would cost more MUFU).
__global__ __launch_bounds__(TOT, 5)
void nerf_render_kernel(
    const float* __restrict__ rays_o, const float* __restrict__ rays_d,
    const float* __restrict__ env,
    const float* __restrict__ gWd1, const float* __restrict__ gWd2,
    const float* __restrict__ gWf1, const float* __restrict__ gWs,
    const float* __restrict__ gWdir, const float* __restrict__ gWrho,
    const float* __restrict__ jitter, const float* __restrict__ u_t,
    const float* __restrict__ u_scatter, const int* __restrict__ channel,
    float* __restrict__ out)
{
    __shared__ float4 sA[HID];          // Wd1 col j: ax, ay, az, 0
    __shared__ ulonglong2 sBxy[HID];    // Wd2 row j: bx dup, by dup
    __shared__ u64 sBz[HID];            // Wd2 row j: bz dup
    __shared__ float2 sBS[HID];         // depth-0 block-uniform {base_j, slope_j}
    __shared__ float4 sUC[HID][2];      // depth-0 uniform {sin u_2p, sin u_2p+1, cos u_2p, cos u_2p+1} for pairs 6,7
    __shared__ float4 sF0[HID];         // Wf1 col j, elems 0..3
    __shared__ float2 sF1[HID];         // Wf1 col j, elems 4..5
    __shared__ float4 sO0[HID];         // Ws[j][0..2], Wdir[j][0]
    __shared__ float4 sO1[HID];         // Wdir[j][1..2], Wrho[j][0..1]
    __shared__ float  sO2[HID];         // Wrho[j][2]
    __shared__ u64    sZp[8][TOT];      // packed z-pairs, [p][tid]: 8B stride -> conflict-free
    __shared__ float  red[4][3];

    int tid = threadIdx.x;
    if (tid < HID) {
        int j = tid;
        sA[j]   = make_float4(gWd1[j], gWd1[64 + j], gWd1[128 + j], 0.0f);
        sBxy[j] = make_ulonglong2(dup_bits(gWd2[j * 3]), dup_bits(gWd2[j * 3 + 1]));
        sBz[j]  = dup_bits(gWd2[j * 3 + 2]);
        sF0[j] = make_float4(gWf1[j], gWf1[64 + j], gWf1[128 + j], gWf1[192 + j]);
        sF1[j] = make_float2(gWf1[256 + j], gWf1[320 + j]);
        sO0[j] = make_float4(gWs[j * 3], gWs[j * 3 + 1], gWs[j * 3 + 2], gWdir[j * 3]);
        sO1[j] = make_float4(gWdir[j * 3 + 1], gWdir[j * 3 + 2], gWrho[j * 3], gWrho[j * 3 + 1]);
        sO2[j] = gWrho[j * 3 + 2];
    }
    __syncthreads();

    int ray = blockIdx.x;
    int m = ray * TOT + tid;

    float ox = rays_o[ray * 3 + 0], oy = rays_o[ray * 3 + 1], oz = rays_o[ray * 3 + 2];
    float dx = rays_d[ray * 3 + 0], dy = rays_d[ray * 3 + 1], dz = rays_d[ray * 3 + 2];
    bool alive = true;
    float thr0 = 1.0f, thr1 = 1.0f, thr2 = 1.0f;
    float rgb0 = 0.0f, rgb1 = 0.0f, rgb2 = 0.0f;

    // packed AA constants (dep-0 tiny-angle polys)
    u64 cone  = bc2(1.0f);
    u64 cm16  = bc2(-0.16666667f);
    u64 cmh   = bc2(-0.5f);

    #pragma unroll
    for (int dep = 0; dep < 2; ++dep) {
        // sphere intersection (needed before the dep-0 uniform tables)
        float a = dx * dx + dy * dy + dz * dz;
        float b = 2.0f * (dx * ox + dy * oy + dz * oz);
        float c = ox * ox + oy * oy + oz * oz - 1.0f;
        float delta = b * b - 4.0f * a * c;
        alive = alive && (delta > 0.0f);
        float sq = sqrtf(fmaxf(delta, 0.0f));
        float twoa = 2.0f * a;
        float nears = fmaxf((-b - sq) / twoa, 0.001f);
        float fars  = fmaxf((-b + sq) / twoa, 0.001f);
        float span = fars - nears;

        // Depth-0 block-uniform precomputes: base/slope dots, and the
        // sincos(u) table for AA pairs 6,7 (samples 12..15 on the nominal grid).
        if (dep == 0) {
            if (tid < HID) {
                float4 aa = sA[tid];
                float base  = fmaf(ox, aa.x, fmaf(oy, aa.y, oz * aa.z));
                float slope = fmaf(dx, aa.x, fmaf(dy, aa.y, dz * aa.z));
                sBS[tid] = make_float2(base, slope);
            }
            __syncthreads();
            {
                int j = tid >> 1;
                int q2 = tid & 1;                  // 0 -> pair 6, 1 -> pair 7
                float2 bs = sBS[j];
                int s0 = 12 + 2 * q2;
                float u0 = fmaf(bs.y, fmaf(span, (float)(s0)     * (1.0f/15.0f), nears), bs.x);
                float u1 = fmaf(bs.y, fmaf(span, (float)(s0 + 1) * (1.0f/15.0f), nears), bs.x);
                sUC[j][q2] = make_float4(__sinf(u0), __sinf(u1), __cosf(u0), __cosf(u1));
            }
            __syncthreads();
        }

        // ---- density over 16 jittered samples ----
        const float4* jp = (const float4*)(jitter + (size_t)dep * (size_t)MTOT * INDS
                                                  + (size_t)m * INDS);
        u64 jv[2];     // dep-0 AA: (jit-0.5)*span/16 for samples 12..15, packed
        {
            float K = span * (1.0f / 16.0f);
            #pragma unroll
            for (int q = 0; q < 4; q++) {
                float4 jvq = jp[q];
                float z0 = nears + span * ((float)(4*q + 0) * (1.0f/15.0f)) + (jvq.x - 0.5f) * K;
                float z1 = nears + span * ((float)(4*q + 1) * (1.0f/15.0f)) + (jvq.y - 0.5f) * K;
                float z2 = nears + span * ((float)(4*q + 2) * (1.0f/15.0f)) + (jvq.z - 0.5f) * K;
                float z3 = nears + span * ((float)(4*q + 3) * (1.0f/15.0f)) + (jvq.w - 0.5f) * K;
                sZp[2*q][tid]     = pk2(z0, z1);
                sZp[2*q + 1][tid] = pk2(z2, z3);
                if (q == 3) {
                    jv[0] = pk2((jvq.x - 0.5f) * K, (jvq.y - 0.5f) * K);
                    jv[1] = pk2((jvq.z - 0.5f) * K, (jvq.w - 0.5f) * K);
                }
            }
        }

        u64 Acc[8][3];
        #pragma unroll
        for (int p = 0; p < 8; p++) { Acc[p][0] = 0; Acc[p][1] = 0; Acc[p][2] = 0; }

        if (dep == 0) {
            #pragma unroll 1
            for (int j = 0; j < HID; j++) {
                float2 bs = sBS[j];
                u64 base2  = bc2(bs.x);
                u64 slope2 = bc2(bs.y);
                ulonglong2 bxy = sBxy[j];
                u64 bz = sBz[j];
                u64 H[8];
                // pairs 0..5: MUFU sin
                #pragma unroll
                for (int p = 0; p < 6; p++)
                    H[p] = sin2_mufu(fma2(sZp[p][tid], slope2, base2));
                // pairs 6,7: angle addition, zero MUFU
                #pragma unroll
                for (int q2 = 0; q2 < 2; q2++) {
                    float4 uc = sUC[j][q2];
                    u64 su2 = pk2(uc.x, uc.y);
                    u64 cu2 = pk2(uc.z, uc.w);
                    u64 v    = mul2(jv[q2], slope2);
                    u64 s2   = mul2(v, v);
                    u64 sinv = mul2(v, fma2(s2, cm16, cone));
                    u64 cosv = fma2(s2, cmh, cone);
                    H[6 + q2] = fma2(cu2, sinv, mul2(su2, cosv));
                }
                #pragma unroll
                for (int p = 0; p < 8; p++) {
                    Acc[p][0] = fma2(H[p], bxy.x, Acc[p][0]);
                    Acc[p][1] = fma2(H[p], bxy.y, Acc[p][1]);
                    Acc[p][2] = fma2(H[p], bz,    Acc[p][2]);
                }
            }
        } else {
            #pragma unroll 1
            for (int j = 0; j < HID; j++) {
                float4 aa = sA[j];
                float base  = fmaf(ox, aa.x, fmaf(oy, aa.y, oz * aa.z));
                float slope = fmaf(dx, aa.x, fmaf(dy, aa.y, dz * aa.z));
                u64 base2  = bc2(base);
                u64 slope2 = bc2(slope);
                ulonglong2 bxy = sBxy[j];
                u64 bz = sBz[j];
                u64 H[8];
                #pragma unroll
                for (int p = 0; p < 8; p++)
                    H[p] = sin2_mufu(fma2(sZp[p][tid], slope2, base2));
                #pragma unroll
                for (int p = 0; p < 8; p++) {
                    Acc[p][0] = fma2(H[p], bxy.x, Acc[p][0]);
                    Acc[p][1] = fma2(H[p], bxy.y, Acc[p][1]);
                    Acc[p][2] = fma2(H[p], bz,    Acc[p][2]);
                }
            }
        }

        // softplus monotone -> reduce raw max per channel, softplus once.
        float rm0 = -1e30f, rm1 = -1e30f, rm2 = -1e30f;
        #pragma unroll
        for (int p = 0; p < 8; p++) {
            float pa, pb;
            upk2(Acc[p][0], pa, pb); rm0 = fmaxf(rm0, fmaxf(pa, pb));
            upk2(Acc[p][1], pa, pb); rm1 = fmaxf(rm1, fmaxf(pa, pb));
            upk2(Acc[p][2], pa, pb); rm2 = fmaxf(rm2, fmaxf(pa, pb));
        }
        float mm0 = fmaxf(softplus_fast(rm0), 0.001f);
        float mm1 = fmaxf(softplus_fast(rm1), 0.001f);
        float mm2 = fmaxf(softplus_fast(rm2), 0.001f);
        float maxm = fmaxf(mm0, fmaxf(mm1, mm2));

        int ch = 0;
        float maj = 0.001f;
        float t;
        if (dep == 0) {
            ch = channel[m];
            maj = (ch == 0) ? mm0 : ((ch == 1) ? mm1 : mm2);
            float ut = u_t[m];
            t = -log1pf(-ut) / maj + nears;   // keep accurate: decides `hit`
        } else {
            t = fars;
        }
        bool hit = alive && (t >= fars);

        float dn0 = __expf(-mm0 * span) / (maxm + EPSF) + EPSF;
        float dn1 = __expf(-mm1 * span) / (maxm + EPSF) + EPSF;
        float dn2 = __expf(-mm2 * span) / (maxm + EPSF) + EPSF;
        float dmean = (dn0 + dn1 + dn2) * (1.0f / 3.0f);

        float Le0, Le1, Le2;
        sample_env(env, fmaf(dx, fars, ox), fmaf(dy, fars, oy), fmaf(dz, fars, oz),
                   Le0, Le1, Le2);

        if (hit) {
            rgb0 += thr0 * (dn0 / dmean) * Le0;
            rgb1 += thr1 * (dn1 / dmean) * Le1;
            rgb2 += thr2 * (dn2 / dmean) * Le2;
        }
        alive = alive && !hit;

        if (dep == 0) {
            float tr0 = __expf(-mm0 * (t - nears)) / maxm;
            float tr1 = __expf(-mm1 * (t - nears)) / maxm;
            float tr2 = __expf(-mm2 * (t - nears)) / maxm;
            float den2 = (mm0 * tr0 + mm1 * tr1 + mm2 * tr2) * (1.0f / 3.0f);
            if (alive) {
                thr0 = thr0 * tr0 / den2;
                thr1 = thr1 * tr1 / den2;
                thr2 = thr2 * tr2 / den2;
                ox = fmaf(dx, t, ox);
                oy = fmaf(dy, t, oy);
                oz = fmaf(dz, t, oz);
            }
            // material MLP on [o, d] (post-update o)
            float st0 = 0.0f, st1 = 0.0f, st2 = 0.0f;
            float v0 = 0.0f, v1 = 0.0f, v2 = 0.0f;
            float rh0 = 0.0f, rh1 = 0.0f, rh2 = 0.0f;
            #pragma unroll 8
            for (int j = 0; j < HID; j++) {
                float4 w0 = sF0[j];
                float2 w1 = sF1[j];
                float u = fmaf(ox, w0.x, fmaf(oy, w0.y, fmaf(oz, w0.z,
                          fmaf(dx, w0.w, fmaf(dy, w1.x, dz * w1.y)))));
                float f = tanh_fast(u);
                float4 p0 = sO0[j];
                float4 p1 = sO1[j];
                float p2 = sO2[j];
                st0 = fmaf(f, p0.x, st0);
                st1 = fmaf(f, p0.y, st1);
                st2 = fmaf(f, p0.z, st2);
                v0  = fmaf(f, p0.w, v0);
                v1  = fmaf(f, p1.x, v1);
                v2  = fmaf(f, p1.y, v2);
                rh0 = fmaf(f, p1.z, rh0);
                rh1 = fmaf(f, p1.w, rh1);
                rh2 = fmaf(f, p2,   rh2);
            }
            st0 = softplus_fast(st0);
            st1 = softplus_fast(st1);
            st2 = softplus_fast(st2);
            float nrm = sqrtf(v0 * v0 + v1 * v1 + v2 * v2);
            float invn = 1.0f / (nrm + EPSF);
            float do0 = v0 * invn, do1 = v1 * invn, do2 = v2 * invn;
            float rho0 = sigmoid_fast(rh0), rho1 = sigmoid_fast(rh1), rho2 = sigmoid_fast(rh2);

            float stch = (ch == 0) ? st0 : ((ch == 1) ? st1 : st2);
            float sp = fminf(stch / maj, 1.0f);
            float us = u_scatter[m];
            bool sm = alive && (us < sp);
            if (sm) {
                dx = do0; dy = do1; dz = do2;
                thr0 = thr0 / (sp + EPSF) * rho0;
                thr1 = thr1 / (sp + EPSF) * rho1;
                thr2 = thr2 / (sp + EPSF) * rho2;
            } else if (alive) {
                float inv = 1.0f / (1.0f - sp + EPSF);
                thr0 *= inv; thr1 *= inv; thr2 *= inv;
            }
        }
    }

    // block reduce: mean over TOT samples of this ray
    #pragma unroll
    for (int off = 16; off > 0; off >>= 1) {
        rgb0 += __shfl_down_sync(0xffffffffu, rgb0, off);
        rgb1 += __shfl_down_sync(0xffffffffu, rgb1, off);
        rgb2 += __shfl_down_sync(0xffffffffu, rgb2, off);
    }
    if ((tid & 31) == 0) {
        red[tid >> 5][0] = rgb0;
        red[tid >> 5][1] = rgb1;
        red[tid >> 5][2] = rgb2;
    }
    __syncthreads();
    if (tid == 0) {
        float a0 = red[0][0] + red[1][0] + red[2][0] + red[3][0];
        float a1 = red[0][1] + red[1][1] + red[2][1] + red[3][1];
        float a2 = red[0][2] + red[1][2] + red[2][2] + red[3][2];
        out[ray * 3 + 0] = a0 * (1.0f / (float)TOT);
        out[ray * 3 + 1] = a1 * (1.0f / (float)TOT);
        out[ray * 3 + 2] = a2 * (1.0f / (float)TOT);
    }
}

extern "C" void kernel_launch(void* const* d_in, const int* in_sizes, int n_in,
                              void* d_out, int out_size) {
    const float* rays_o    = (const float*)d_in[0];
    const float* rays_d    = (const float*)d_in[1];
    const float* env       = (const float*)d_in[2];
    const float* Wd1       = (const float*)d_in[3];
    const float* Wd2       = (const float*)d_in[4];
    const float* Wf1       = (const float*)d_in[5];
    const float* Ws        = (const float*)d_in[6];
    const float* Wdir      = (const float*)d_in[7];
    const float* Wrho      = (const float*)d_in[8];
    const float* jitter    = (const float*)d_in[9];
    const float* u_t       = (const float*)d_in[10];
    const float* u_scatter = (const float*)d_in[11];
    const int*   channel   = (const int*)d_in[12];
    float* out = (float*)d_out;

    nerf_render_kernel<<<NRAYS, TOT>>>(rays_o, rays_d, env, Wd1, Wd2, Wf1, Ws,
                                       Wdir, Wrho, jitter, u_t, u_scatter,
                                       channel, out);
}

// round 13
// speedup vs baseline: 1.1499x; 1.0417x over previous
#include <cuda_runtime.h>
#include <math.h>

#define NRAYS 2048
#define TOT 128
#define INDS 16
#define HID 64
#define MTOT (NRAYS*TOT)
#define EPSF 1e-8f

typedef unsigned long long u64;

// ---------------- f32x2 packed helpers (sm_103a) ----------------
__device__ __forceinline__ u64 pk2(float lo, float hi) {
    u64 r; asm("mov.b64 %0, {%1,%2};" : "=l"(r) : "f"(lo), "f"(hi)); return r;
}
__device__ __forceinline__ u64 bc2(float v) {
    u64 r; asm("mov.b64 %0, {%1,%1};" : "=l"(r) : "f"(v)); return r;
}
__device__ __forceinline__ void upk2(u64 a, float& lo, float& hi) {
    asm("mov.b64 {%0,%1}, %2;" : "=f"(lo), "=f"(hi) : "l"(a));
}
__device__ __forceinline__ u64 fma2(u64 a, u64 b, u64 c) {
    u64 d; asm("fma.rn.f32x2 %0, %1, %2, %3;" : "=l"(d) : "l"(a), "l"(b), "l"(c)); return d;
}
__device__ __forceinline__ u64 mul2(u64 a, u64 b) {
    u64 d; asm("mul.rn.f32x2 %0, %1, %2;" : "=l"(d) : "l"(a), "l"(b)); return d;
}

// MUFU sin pair: 2 SFU-pipe instructions, zero FMA-pipe cost.
__device__ __forceinline__ u64 sin2_mufu(u64 x) {
    float lo, hi; upk2(x, lo, hi);
    return pk2(__sinf(lo), __sinf(hi));
}

// ---------------- scalar helpers (fast-math epilogue) ----------------
__device__ __forceinline__ float tanh_fast(float x) {
    float ax = fminf(fabsf(x), 10.0f);
    float e = __expf(2.0f * ax);
    float t = __fdividef(e - 1.0f, e + 1.0f);
    return (x < 0.0f) ? -t : t;
}
__device__ __forceinline__ float softplus_fast(float x) {
    return fmaxf(x, 0.0f) + __logf(1.0f + __expf(-fabsf(x)));
}
__device__ __forceinline__ float sigmoid_fast(float x) {
    float e = __expf(-fabsf(x));
    float r = __fdividef(1.0f, 1.0f + e);
    return (x >= 0.0f) ? r : (1.0f - r);
}

// ---------------- env map bilinear sample ----------------
__device__ __forceinline__ void sample_env(const float* __restrict__ env,
                                           float px, float py, float pz,
                                           float& Le0, float& Le1, float& Le2) {
    const float INV_PI = 0.3183098861837907f;
    float theta = atan2f(px, -pz);
    if (isnan(theta)) theta = 0.0f;
    theta *= INV_PI;
    float ac = acosf(py);
    if (isnan(ac)) ac = 0.0f;
    float phi = fmaf(ac, 2.0f * INV_PI, -1.0f);

    float ix = ((theta + 1.0f) * 256.0f - 1.0f) * 0.5f;
    float iy = ((phi   + 1.0f) * 128.0f - 1.0f) * 0.5f;
    float x0 = floorf(ix), y0 = floorf(iy);
    float wx = ix - x0,    wy = iy - y0;

    float v0 = 0.0f, v1 = 0.0f, v2 = 0.0f;
    #pragma unroll
    for (int t = 0; t < 4; t++) {
        float xc = x0 + (float)(t & 1);
        float yc = y0 + (float)(t >> 1);
        float w = ((t & 1) ? wx : (1.0f - wx)) * ((t >> 1) ? wy : (1.0f - wy));
        bool inb = (xc >= 0.0f) && (xc < 256.0f) && (yc >= 0.0f) && (yc < 128.0f);
        float wi = inb ? w : 0.0f;
        int xi = (int)fminf(fmaxf(xc, 0.0f), 255.0f);
        int yi = (int)fminf(fmaxf(yc, 0.0f), 127.0f);
        int base = yi * 256 + xi;
        v0 = fmaf(wi, env[base],         v0);
        v1 = fmaf(wi, env[32768 + base], v1);
        v2 = fmaf(wi, env[65536 + base], v2);
    }
    Le0 = __expf(v0); Le1 = __expf(v1); Le2 = __expf(v2);
}

__device__ __forceinline__ u64 dup_bits(float v) {
    u64 b = (u64)__float_as_uint(v);
    return b | (b << 32);
}

// ---------------- main fused renderer: 1 block = 1 ray, 1 thread = 1 sample ----------------
// Depth 0: 6 of 8 sample-pairs via MUFU sin; 2 pairs via angle-addition with
// block-uniform sincos(u) table (smem). Depth 1: all-MUFU. Both density
// loops unrolled x2 for software pipelining (overlap j+1 args/LDS with j's
// MUFU window) — MUFU duty is the binder at ~68%.
__global__ __launch_bounds__(TOT, 4)
void nerf_render_kernel(
    const float* __restrict__ rays_o, const float* __restrict__ rays_d,
    const float* __restrict__ env,
    const float* __restrict__ gWd1, const float* __restrict__ gWd2,
    const float* __restrict__ gWf1, const float* __restrict__ gWs,
    const float* __restrict__ gWdir, const float* __restrict__ gWrho,
    const float* __restrict__ jitter, const float* __restrict__ u_t,
    const float* __restrict__ u_scatter, const int* __restrict__ channel,
    float* __restrict__ out)
{
    __shared__ float4 sA[HID];          // Wd1 col j: ax, ay, az, 0
    __shared__ ulonglong2 sBxy[HID];    // Wd2 row j: bx dup, by dup
    __shared__ u64 sBz[HID];            // Wd2 row j: bz dup
    __shared__ float2 sBS[HID];         // depth-0 block-uniform {base_j, slope_j}
    __shared__ float4 sUC[HID][2];      // depth-0 uniform sincos(u) for AA pairs 6,7
    __shared__ float4 sF0[HID];         // Wf1 col j, elems 0..3
    __shared__ float2 sF1[HID];         // Wf1 col j, elems 4..5
    __shared__ float4 sO0[HID];         // Ws[j][0..2], Wdir[j][0]
    __shared__ float4 sO1[HID];         // Wdir[j][1..2], Wrho[j][0..1]
    __shared__ float  sO2[HID];         // Wrho[j][2]
    __shared__ u64    sZp[8][TOT];      // packed z-pairs, [p][tid]: 8B stride -> conflict-free
    __shared__ float  red[4][3];

    int tid = threadIdx.x;
    if (tid < HID) {
        int j = tid;
        sA[j]   = make_float4(gWd1[j], gWd1[64 + j], gWd1[128 + j], 0.0f);
        sBxy[j] = make_ulonglong2(dup_bits(gWd2[j * 3]), dup_bits(gWd2[j * 3 + 1]));
        sBz[j]  = dup_bits(gWd2[j * 3 + 2]);
        sF0[j] = make_float4(gWf1[j], gWf1[64 + j], gWf1[128 + j], gWf1[192 + j]);
        sF1[j] = make_float2(gWf1[256 + j], gWf1[320 + j]);
        sO0[j] = make_float4(gWs[j * 3], gWs[j * 3 + 1], gWs[j * 3 + 2], gWdir[j * 3]);
        sO1[j] = make_float4(gWdir[j * 3 + 1], gWdir[j * 3 + 2], gWrho[j * 3], gWrho[j * 3 + 1]);
        sO2[j] = gWrho[j * 3 + 2];
    }
    __syncthreads();

    int ray = blockIdx.x;
    int m = ray * TOT + tid;

    float ox = rays_o[ray * 3 + 0], oy = rays_o[ray * 3 + 1], oz = rays_o[ray * 3 + 2];
    float dx = rays_d[ray * 3 + 0], dy = rays_d[ray * 3 + 1], dz = rays_d[ray * 3 + 2];
    bool alive = true;
    float thr0 = 1.0f, thr1 = 1.0f, thr2 = 1.0f;
    float rgb0 = 0.0f, rgb1 = 0.0f, rgb2 = 0.0f;

    // packed AA constants (dep-0 tiny-angle polys)
    u64 cone  = bc2(1.0f);
    u64 cm16  = bc2(-0.16666667f);
    u64 cmh   = bc2(-0.5f);

    #pragma unroll
    for (int dep = 0; dep < 2; ++dep) {
        // sphere intersection (needed before the dep-0 uniform tables)
        float a = dx * dx + dy * dy + dz * dz;
        float b = 2.0f * (dx * ox + dy * oy + dz * oz);
        float c = ox * ox + oy * oy + oz * oz - 1.0f;
        float delta = b * b - 4.0f * a * c;
        alive = alive && (delta > 0.0f);
        float sq = sqrtf(fmaxf(delta, 0.0f));
        float twoa = 2.0f * a;
        float nears = fmaxf((-b - sq) / twoa, 0.001f);
        float fars  = fmaxf((-b + sq) / twoa, 0.001f);
        float span = fars - nears;

        // Depth-0 block-uniform precomputes: base/slope dots, and the
        // sincos(u) table for AA pairs 6,7 (samples 12..15 on the nominal grid).
        if (dep == 0) {
            if (tid < HID) {
                float4 aa = sA[tid];
                float base  = fmaf(ox, aa.x, fmaf(oy, aa.y, oz * aa.z));
                float slope = fmaf(dx, aa.x, fmaf(dy, aa.y, dz * aa.z));
                sBS[tid] = make_float2(base, slope);
            }
            __syncthreads();
            {
                int j = tid >> 1;
                int q2 = tid & 1;                  // 0 -> pair 6, 1 -> pair 7
                float2 bs = sBS[j];
                int s0 = 12 + 2 * q2;
                float u0 = fmaf(bs.y, fmaf(span, (float)(s0)     * (1.0f/15.0f), nears), bs.x);
                float u1 = fmaf(bs.y, fmaf(span, (float)(s0 + 1) * (1.0f/15.0f), nears), bs.x);
                sUC[j][q2] = make_float4(__sinf(u0), __sinf(u1), __cosf(u0), __cosf(u1));
            }
            __syncthreads();
        }

        // ---- density over 16 jittered samples ----
        const float4* jp = (const float4*)(jitter + (size_t)dep * (size_t)MTOT * INDS
                                                  + (size_t)m * INDS);
        u64 jv[2];     // dep-0 AA: (jit-0.5)*span/16 for samples 12..15, packed
        {
            float K = span * (1.0f / 16.0f);
            #pragma unroll
            for (int q = 0; q < 4; q++) {
                float4 jvq = jp[q];
                float z0 = nears + span * ((float)(4*q + 0) * (1.0f/15.0f)) + (jvq.x - 0.5f) * K;
                float z1 = nears + span * ((float)(4*q + 1) * (1.0f/15.0f)) + (jvq.y - 0.5f) * K;
                float z2 = nears + span * ((float)(4*q + 2) * (1.0f/15.0f)) + (jvq.z - 0.5f) * K;
                float z3 = nears + span * ((float)(4*q + 3) * (1.0f/15.0f)) + (jvq.w - 0.5f) * K;
                sZp[2*q][tid]     = pk2(z0, z1);
                sZp[2*q + 1][tid] = pk2(z2, z3);
                if (q == 3) {
                    jv[0] = pk2((jvq.x - 0.5f) * K, (jvq.y - 0.5f) * K);
                    jv[1] = pk2((jvq.z - 0.5f) * K, (jvq.w - 0.5f) * K);
                }
            }
        }

        u64 Acc[8][3];
        #pragma unroll
        for (int p = 0; p < 8; p++) { Acc[p][0] = 0; Acc[p][1] = 0; Acc[p][2] = 0; }

        if (dep == 0) {
            #pragma unroll 2
            for (int j = 0; j < HID; j++) {
                float2 bs = sBS[j];
                u64 base2  = bc2(bs.x);
                u64 slope2 = bc2(bs.y);
                ulonglong2 bxy = sBxy[j];
                u64 bz = sBz[j];
                u64 H[8];
                // pairs 0..5: MUFU sin
                #pragma unroll
                for (int p = 0; p < 6; p++)
                    H[p] = sin2_mufu(fma2(sZp[p][tid], slope2, base2));
                // pairs 6,7: angle addition, zero MUFU
                #pragma unroll
                for (int q2 = 0; q2 < 2; q2++) {
                    float4 uc = sUC[j][q2];
                    u64 su2 = pk2(uc.x, uc.y);
                    u64 cu2 = pk2(uc.z, uc.w);
                    u64 v    = mul2(jv[q2], slope2);
                    u64 s2   = mul2(v, v);
                    u64 sinv = mul2(v, fma2(s2, cm16, cone));
                    u64 cosv = fma2(s2, cmh, cone);
                    H[6 + q2] = fma2(cu2, sinv, mul2(su2, cosv));
                }
                #pragma unroll
                for (int p = 0; p < 8; p++) {
                    Acc[p][0] = fma2(H[p], bxy.x, Acc[p][0]);
                    Acc[p][1] = fma2(H[p], bxy.y, Acc[p][1]);
                    Acc[p][2] = fma2(H[p], bz,    Acc[p][2]);
                }
            }
        } else {
            #pragma unroll 2
            for (int j = 0; j < HID; j++) {
                float4 aa = sA[j];
                float base  = fmaf(ox, aa.x, fmaf(oy, aa.y, oz * aa.z));
                float slope = fmaf(dx, aa.x, fmaf(dy, aa.y, dz * aa.z));
                u64 base2  = bc2(base);
                u64 slope2 = bc2(slope);
                ulonglong2 bxy = sBxy[j];
                u64 bz = sBz[j];
                u64 H[8];
                #pragma unroll
                for (int p = 0; p < 8; p++)
                    H[p] = sin2_mufu(fma2(sZp[p][tid], slope2, base2));
                #pragma unroll
                for (int p = 0; p < 8; p++) {
                    Acc[p][0] = fma2(H[p], bxy.x, Acc[p][0]);
                    Acc[p][1] = fma2(H[p], bxy.y, Acc[p][1]);
                    Acc[p][2] = fma2(H[p], bz,    Acc[p][2]);
                }
            }
        }

        // softplus monotone -> reduce raw max per channel, softplus once.
        float rm0 = -1e30f, rm1 = -1e30f, rm2 = -1e30f;
        #pragma unroll
        for (int p = 0; p < 8; p++) {
            float pa, pb;
            upk2(Acc[p][0], pa, pb); rm0 = fmaxf(rm0, fmaxf(pa, pb));
            upk2(Acc[p][1], pa, pb); rm1 = fmaxf(rm1, fmaxf(pa, pb));
            upk2(Acc[p][2], pa, pb); rm2 = fmaxf(rm2, fmaxf(pa, pb));
        }
        float mm0 = fmaxf(softplus_fast(rm0), 0.001f);
        float mm1 = fmaxf(softplus_fast(rm1), 0.001f);
        float mm2 = fmaxf(softplus_fast(rm2), 0.001f);
        float maxm = fmaxf(mm0, fmaxf(mm1, mm2));

        int ch = 0;
        float maj = 0.001f;
        float t;
        if (dep == 0) {
            ch = channel[m];
            maj = (ch == 0) ? mm0 : ((ch == 1) ? mm1 : mm2);
            float ut = u_t[m];
            t = -log1pf(-ut) / maj + nears;   // keep accurate: decides `hit`
        } else {
            t = fars;
        }
        bool hit = alive && (t >= fars);

        float dn0 = __expf(-mm0 * span) / (maxm + EPSF) + EPSF;
        float dn1 = __expf(-mm1 * span) / (maxm + EPSF) + EPSF;
        float dn2 = __expf(-mm2 * span) / (maxm + EPSF) + EPSF;
        float dmean = (dn0 + dn1 + dn2) * (1.0f / 3.0f);

        float Le0, Le1, Le2;
        sample_env(env, fmaf(dx, fars, ox), fmaf(dy, fars, oy), fmaf(dz, fars, oz),
                   Le0, Le1, Le2);

        if (hit) {
            rgb0 += thr0 * (dn0 / dmean) * Le0;
            rgb1 += thr1 * (dn1 / dmean) * Le1;
            rgb2 += thr2 * (dn2 / dmean) * Le2;
        }
        alive = alive && !hit;

        if (dep == 0) {
            float tr0 = __expf(-mm0 * (t - nears)) / maxm;
            float tr1 = __expf(-mm1 * (t - nears)) / maxm;
            float tr2 = __expf(-mm2 * (t - nears)) / maxm;
            float den2 = (mm0 * tr0 + mm1 * tr1 + mm2 * tr2) * (1.0f / 3.0f);
            if (alive) {
                thr0 = thr0 * tr0 / den2;
                thr1 = thr1 * tr1 / den2;
                thr2 = thr2 * tr2 / den2;
                ox = fmaf(dx, t, ox);
                oy = fmaf(dy, t, oy);
                oz = fmaf(dz, t, oz);
            }
            // material MLP on [o, d] (post-update o)
            float st0 = 0.0f, st1 = 0.0f, st2 = 0.0f;
            float v0 = 0.0f, v1 = 0.0f, v2 = 0.0f;
            float rh0 = 0.0f, rh1 = 0.0f, rh2 = 0.0f;
            #pragma unroll 8
            for (int j = 0; j < HID; j++) {
                float4 w0 = sF0[j];
                float2 w1 = sF1[j];
                float u = fmaf(ox, w0.x, fmaf(oy, w0.y, fmaf(oz, w0.z,
                          fmaf(dx, w0.w, fmaf(dy, w1.x, dz * w1.y)))));
                float f = tanh_fast(u);
                float4 p0 = sO0[j];
                float4 p1 = sO1[j];
                float p2 = sO2[j];
                st0 = fmaf(f, p0.x, st0);
                st1 = fmaf(f, p0.y, st1);
                st2 = fmaf(f, p0.z, st2);
                v0  = fmaf(f, p0.w, v0);
                v1  = fmaf(f, p1.x, v1);
                v2  = fmaf(f, p1.y, v2);
                rh0 = fmaf(f, p1.z, rh0);
                rh1 = fmaf(f, p1.w, rh1);
                rh2 = fmaf(f, p2,   rh2);
            }
            st0 = softplus_fast(st0);
            st1 = softplus_fast(st1);
            st2 = softplus_fast(st2);
            float nrm = sqrtf(v0 * v0 + v1 * v1 + v2 * v2);
            float invn = 1.0f / (nrm + EPSF);
            float do0 = v0 * invn, do1 = v1 * invn, do2 = v2 * invn;
            float rho0 = sigmoid_fast(rh0), rho1 = sigmoid_fast(rh1), rho2 = sigmoid_fast(rh2);

            float stch = (ch == 0) ? st0 : ((ch == 1) ? st1 : st2);
            float sp = fminf(stch / maj, 1.0f);
            float us = u_scatter[m];
            bool sm = alive && (us < sp);
            if (sm) {
                dx = do0; dy = do1; dz = do2;
                thr0 = thr0 / (sp + EPSF) * rho0;
                thr1 = thr1 / (sp + EPSF) * rho1;
                thr2 = thr2 / (sp + EPSF) * rho2;
            } else if (alive) {
                float inv = 1.0f / (1.0f - sp + EPSF);
                thr0 *= inv; thr1 *= inv; thr2 *= inv;
            }
        }
    }

    // block reduce: mean over TOT samples of this ray
    #pragma unroll
    for (int off = 16; off > 0; off >>= 1) {
        rgb0 += __shfl_down_sync(0xffffffffu, rgb0, off);
        rgb1 += __shfl_down_sync(0xffffffffu, rgb1, off);
        rgb2 += __shfl_down_sync(0xffffffffu, rgb2, off);
    }
    if ((tid & 31) == 0) {
        red[tid >> 5][0] = rgb0;
        red[tid >> 5][1] = rgb1;
        red[tid >> 5][2] = rgb2;
    }
    __syncthreads();
    if (tid == 0) {
        float a0 = red[0][0] + red[1][0] + red[2][0] + red[3][0];
        float a1 = red[0][1] + red[1][1] + red[2][1] + red[3][1];
        float a2 = red[0][2] + red[1][2] + red[2][2] + red[3][2];
        out[ray * 3 + 0] = a0 * (1.0f / (float)TOT);
        out[ray * 3 + 1] = a1 * (1.0f / (float)TOT);
        out[ray * 3 + 2] = a2 * (1.0f / (float)TOT);
    }
}

extern "C" void kernel_launch(void* const* d_in, const int* in_sizes, int n_in,
                              void* d_out, int out_size) {
    const float* rays_o    = (const float*)d_in[0];
    const float* rays_d    = (const float*)d_in[1];
    const float* env       = (const float*)d_in[2];
    const float* Wd1       = (const float*)d_in[3];
    const float* Wd2       = (const float*)d_in[4];
    const float* Wf1       = (const float*)d_in[5];
    const float* Ws        = (const float*)d_in[6];
    const float* Wdir      = (const float*)d_in[7];
    const float* Wrho      = (const float*)d_in[8];
    const float* jitter    = (const float*)d_in[9];
    const float* u_t       = (const float*)d_in[10];
    const float* u_scatter = (const float*)d_in[11];
    const int*   channel   = (const int*)d_in[12];
    float* out = (float*)d_out;

    nerf_render_kernel<<<NRAYS, TOT>>>(rays_o, rays_d, env, Wd1, Wd2, Wf1, Ws,
                                       Wdir, Wrho, jitter, u_t, u_scatter,
                                       channel, out);
}